// round 1
// baseline (speedup 1.0000x reference)
#include <cuda_runtime.h>
#include <cuda_bf16.h>
#include <cstdint>

// Problem constants
#define NN    8192
#define F_IN  512
#define F_OUT 256
#define ALPHA 0.2f
#define NEG_INF (-9e15f)

// -------- scratch (device globals: no allocations allowed) ----------------
__device__ float g_h[NN * F_OUT];   // h = x @ W         (8 MB)
__device__ float g_f1[NN];          // h @ a[:256]
__device__ float g_f2[NN];          // h @ a[256:]

// ===========================================================================
// Kernel 1: h = x @ W      (8192x512 @ 512x256)
// 64x64 tile, BK=16, 256 threads, 4x4 microtile.
// ===========================================================================
__global__ __launch_bounds__(256) void gemm1_kernel(
    const float* __restrict__ X, const float* __restrict__ W)
{
    __shared__ float Xs[16][64];   // transposed: [k][m]
    __shared__ float Ws[16][64];

    const int t   = threadIdx.x;
    const int tx  = t & 15;        // 0..15 col group
    const int ty  = t >> 4;        // 0..15 row group
    const int row0 = blockIdx.x * 64;
    const int col0 = blockIdx.y * 64;

    float acc[4][4];
#pragma unroll
    for (int i = 0; i < 4; ++i)
#pragma unroll
        for (int j = 0; j < 4; ++j) acc[i][j] = 0.f;

    for (int k0 = 0; k0 < F_IN; k0 += 16) {
        // Load X tile (64 rows x 16 k), transpose into Xs
        {
            int r  = t >> 2;             // 0..63
            int kq = (t & 3) * 4;        // 0,4,8,12
            float4 v = *(const float4*)&X[(size_t)(row0 + r) * F_IN + k0 + kq];
            Xs[kq + 0][r] = v.x;
            Xs[kq + 1][r] = v.y;
            Xs[kq + 2][r] = v.z;
            Xs[kq + 3][r] = v.w;
        }
        // Load W tile (16 k x 64 cols)
        {
            int kr = t >> 4;             // 0..15
            int cq = (t & 15) * 4;       // 0..60
            *(float4*)&Ws[kr][cq] =
                *(const float4*)&W[(size_t)(k0 + kr) * F_OUT + col0 + cq];
        }
        __syncthreads();

#pragma unroll
        for (int kk = 0; kk < 16; ++kk) {
            float a4[4], b4[4];
            *(float4*)a4 = *(const float4*)&Xs[kk][ty * 4];
            *(float4*)b4 = *(const float4*)&Ws[kk][tx * 4];
#pragma unroll
            for (int i = 0; i < 4; ++i)
#pragma unroll
                for (int j = 0; j < 4; ++j)
                    acc[i][j] = fmaf(a4[i], b4[j], acc[i][j]);
        }
        __syncthreads();
    }

#pragma unroll
    for (int i = 0; i < 4; ++i) {
        float4 v = make_float4(acc[i][0], acc[i][1], acc[i][2], acc[i][3]);
        *(float4*)&g_h[(size_t)(row0 + ty * 4 + i) * F_OUT + col0 + tx * 4] = v;
    }
}

// ===========================================================================
// Kernel 2: f1[i] = h[i,:] . a[0:256],  f2[i] = h[i,:] . a[256:512]
// One warp per row.
// ===========================================================================
__global__ __launch_bounds__(256) void f12_kernel(const float* __restrict__ a)
{
    const int warp = threadIdx.x >> 5;
    const int lane = threadIdx.x & 31;
    const int row  = blockIdx.x * 8 + warp;
    if (row >= NN) return;

    const float* hr = &g_h[(size_t)row * F_OUT];
    float s1 = 0.f, s2 = 0.f;
#pragma unroll
    for (int q = 0; q < 8; ++q) {
        int f = lane + q * 32;
        float v = hr[f];
        s1 = fmaf(v, a[f], s1);
        s2 = fmaf(v, a[F_OUT + f], s2);
    }
#pragma unroll
    for (int off = 16; off > 0; off >>= 1) {
        s1 += __shfl_xor_sync(0xffffffffu, s1, off);
        s2 += __shfl_xor_sync(0xffffffffu, s2, off);
    }
    if (lane == 0) { g_f1[row] = s1; g_f2[row] = s2; }
}

// ===========================================================================
// Kernel 3: fused masked-softmax attention + att@h + ELU  (flash style)
// Block: 128 threads, BM=32 rows, BN=32 j per tile.
//   softmax role: thread t -> row sr=t>>2, j-subrange sj=(t&3)*8 (8 j each)
//   gemm role:    thread t -> rows rg*8..rg*8+7 (rg=t>>5),
//                 cols {4*cg..4*cg+3} U {128+4*cg..+3} (cg=t&31)
// ===========================================================================
#define BM 32
#define BN 32

__global__ __launch_bounds__(128) void gat_kernel(
    const int* __restrict__ adj, float* __restrict__ out)
{
    __shared__ float h_s[BN][F_OUT];      // 32 KB
    __shared__ float p_s[BN][BM + 4];     // transposed p, padded
    __shared__ float scale_s[BM];
    __shared__ float l_s[BM];

    const int t = threadIdx.x;
    const int rowbase = blockIdx.x * BM;

    // softmax mapping
    const int sr = t >> 2;           // 0..31
    const int sj = (t & 3) * 8;      // 0,8,16,24
    const float f1v = g_f1[rowbase + sr];
    float m = -3.402823466e38f;      // running max
    float l = 0.f;                   // running denom

    // gemm mapping
    const int rg  = t >> 5;          // 0..3
    const int cg4 = (t & 31) * 4;    // 0..124

    float acc[8][8];
#pragma unroll
    for (int rr = 0; rr < 8; ++rr)
#pragma unroll
        for (int cc = 0; cc < 8; ++cc) acc[rr][cc] = 0.f;

    for (int j0 = 0; j0 < NN; j0 += BN) {
        // ---- stage h tile [BN x 256] -----------------------------------
#pragma unroll
        for (int q = 0; q < 16; ++q) {
            int idx = q * 512 + t * 4;           // 0..8188
            int jj = idx >> 8;                   // 0..31
            int ff = idx & 255;
            *(float4*)&h_s[jj][ff] =
                *(const float4*)&g_h[(size_t)(j0 + jj) * F_OUT + ff];
        }

        // ---- online softmax for this tile ------------------------------
        const int* arow = adj + (size_t)(rowbase + sr) * NN + j0 + sj;
        int4   A0 = *(const int4*)arow;
        int4   A1 = *(const int4*)(arow + 4);
        float4 F0 = *(const float4*)&g_f2[j0 + sj];
        float4 F1 = *(const float4*)&g_f2[j0 + sj + 4];

        int   av[8] = {A0.x, A0.y, A0.z, A0.w, A1.x, A1.y, A1.z, A1.w};
        float fv[8] = {F0.x, F0.y, F0.z, F0.w, F1.x, F1.y, F1.z, F1.w};
        float sv[8];
#pragma unroll
        for (int k = 0; k < 8; ++k) {
            float e = f1v + fv[k];
            e = (e > 0.f) ? e : ALPHA * e;       // leaky relu
            sv[k] = (av[k] > 0) ? e : NEG_INF;   // mask
        }
        float tm = sv[0];
#pragma unroll
        for (int k = 1; k < 8; ++k) tm = fmaxf(tm, sv[k]);
        tm = fmaxf(tm, __shfl_xor_sync(0xffffffffu, tm, 1));
        tm = fmaxf(tm, __shfl_xor_sync(0xffffffffu, tm, 2));

        float mnew = fmaxf(m, tm);
        float p[8], psum = 0.f;
#pragma unroll
        for (int k = 0; k < 8; ++k) {
            p[k] = __expf(sv[k] - mnew);
            psum += p[k];
        }
        psum += __shfl_xor_sync(0xffffffffu, psum, 1);
        psum += __shfl_xor_sync(0xffffffffu, psum, 2);

        float sc = __expf(m - mnew);
        l = l * sc + psum;
        m = mnew;
        if ((t & 3) == 0) scale_s[sr] = sc;
#pragma unroll
        for (int k = 0; k < 8; ++k) p_s[sj + k][sr] = p[k];

        __syncthreads();

        // ---- rescale accumulators (uniform branch per warp) ------------
#pragma unroll
        for (int rr = 0; rr < 8; ++rr) {
            float s = scale_s[rg * 8 + rr];
            if (s != 1.f) {
#pragma unroll
                for (int cc = 0; cc < 8; ++cc) acc[rr][cc] *= s;
            }
        }

        // ---- microtile GEMM: acc += p^T-tile @ h-tile ------------------
#pragma unroll
        for (int j = 0; j < BN; ++j) {
            float4 pa = *(const float4*)&p_s[j][rg * 8];
            float4 pb = *(const float4*)&p_s[j][rg * 8 + 4];
            float4 h0 = *(const float4*)&h_s[j][cg4];
            float4 h1 = *(const float4*)&h_s[j][cg4 + 128];
            float pr[8] = {pa.x, pa.y, pa.z, pa.w, pb.x, pb.y, pb.z, pb.w};
            float hv[8] = {h0.x, h0.y, h0.z, h0.w, h1.x, h1.y, h1.z, h1.w};
#pragma unroll
            for (int rr = 0; rr < 8; ++rr)
#pragma unroll
                for (int cc = 0; cc < 8; ++cc)
                    acc[rr][cc] = fmaf(pr[rr], hv[cc], acc[rr][cc]);
        }
        __syncthreads();
    }

    // ---- epilogue: divide by l, ELU, store ----------------------------
    if ((t & 3) == 0) l_s[sr] = l;
    __syncthreads();

#pragma unroll
    for (int rr = 0; rr < 8; ++rr) {
        int row = rowbase + rg * 8 + rr;
        float inv = 1.f / l_s[rg * 8 + rr];
        float v[8];
#pragma unroll
        for (int cc = 0; cc < 8; ++cc) {
            float x = acc[rr][cc] * inv;
            v[cc] = (x > 0.f) ? x : (__expf(x) - 1.f);   // elu, alpha=1
        }
        *(float4*)&out[(size_t)row * F_OUT + cg4] =
            make_float4(v[0], v[1], v[2], v[3]);
        *(float4*)&out[(size_t)row * F_OUT + cg4 + 128] =
            make_float4(v[4], v[5], v[6], v[7]);
    }
}

// ===========================================================================
// launch
// ===========================================================================
extern "C" void kernel_launch(void* const* d_in, const int* in_sizes, int n_in,
                              void* d_out, int out_size)
{
    const float* x   = (const float*)d_in[0];   // [8192, 512]
    const int*   adj = (const int*)  d_in[1];   // [8192, 8192]
    const float* W   = (const float*)d_in[2];   // [512, 256]
    const float* a   = (const float*)d_in[3];   // [512, 1]
    float* out = (float*)d_out;                 // [8192, 256]

    gemm1_kernel<<<dim3(NN / 64, F_OUT / 64), 256>>>(x, W);
    f12_kernel<<<NN / 8, 256>>>(a);
    gat_kernel<<<NN / BM, 128>>>(adj, out);
}

// round 3
// speedup vs baseline: 1.8329x; 1.8329x over previous
#include <cuda_runtime.h>
#include <cuda_bf16.h>
#include <cstdint>

// Problem constants
#define NN    8192
#define F_IN  512
#define F_OUT 256
#define ALPHA 0.2f
#define NEG_INF (-9e15f)

// -------- scratch (device globals: no allocations allowed) ----------------
__device__ float g_h [NN * F_OUT];  // h = x @ W (fp32, for f1/f2)
__device__ float g_ht[NN * F_OUT];  // h pre-rounded to tf32 (for mma B operand)
__device__ float g_f1[NN];
__device__ float g_f2[NN];
__device__ float g_m [NN];          // row max of masked scores
__device__ float g_il[NN];          // 1 / row softmax denom

__device__ __forceinline__ float to_tf32(float x) {
    uint32_t r;
    asm("cvt.rna.tf32.f32 %0, %1;" : "=r"(r) : "f"(x));
    return __uint_as_float(r);
}

// ===========================================================================
// Kernel 1: h = x @ W      (8192x512 @ 512x256), also writes tf32 copy
// ===========================================================================
__global__ __launch_bounds__(256) void gemm1_kernel(
    const float* __restrict__ X, const float* __restrict__ W)
{
    __shared__ float Xs[16][64];
    __shared__ float Ws[16][64];

    const int t   = threadIdx.x;
    const int tx  = t & 15;
    const int ty  = t >> 4;
    const int row0 = blockIdx.x * 64;
    const int col0 = blockIdx.y * 64;

    float acc[4][4];
#pragma unroll
    for (int i = 0; i < 4; ++i)
#pragma unroll
        for (int j = 0; j < 4; ++j) acc[i][j] = 0.f;

    for (int k0 = 0; k0 < F_IN; k0 += 16) {
        {
            int r  = t >> 2;
            int kq = (t & 3) * 4;
            float4 v = *(const float4*)&X[(size_t)(row0 + r) * F_IN + k0 + kq];
            Xs[kq + 0][r] = v.x;
            Xs[kq + 1][r] = v.y;
            Xs[kq + 2][r] = v.z;
            Xs[kq + 3][r] = v.w;
        }
        {
            int kr = t >> 4;
            int cq = (t & 15) * 4;
            *(float4*)&Ws[kr][cq] =
                *(const float4*)&W[(size_t)(k0 + kr) * F_OUT + col0 + cq];
        }
        __syncthreads();

#pragma unroll
        for (int kk = 0; kk < 16; ++kk) {
            float a4[4], b4[4];
            *(float4*)a4 = *(const float4*)&Xs[kk][ty * 4];
            *(float4*)b4 = *(const float4*)&Ws[kk][tx * 4];
#pragma unroll
            for (int i = 0; i < 4; ++i)
#pragma unroll
                for (int j = 0; j < 4; ++j)
                    acc[i][j] = fmaf(a4[i], b4[j], acc[i][j]);
        }
        __syncthreads();
    }

#pragma unroll
    for (int i = 0; i < 4; ++i) {
        size_t off = (size_t)(row0 + ty * 4 + i) * F_OUT + col0 + tx * 4;
        *(float4*)&g_h[off] = make_float4(acc[i][0], acc[i][1], acc[i][2], acc[i][3]);
        *(float4*)&g_ht[off] = make_float4(to_tf32(acc[i][0]), to_tf32(acc[i][1]),
                                           to_tf32(acc[i][2]), to_tf32(acc[i][3]));
    }
}

// ===========================================================================
// Kernel 2: f1 / f2 row dot products
// ===========================================================================
__global__ __launch_bounds__(256) void f12_kernel(const float* __restrict__ a)
{
    const int warp = threadIdx.x >> 5;
    const int lane = threadIdx.x & 31;
    const int row  = blockIdx.x * 8 + warp;
    if (row >= NN) return;

    const float* hr = &g_h[(size_t)row * F_OUT];
    float s1 = 0.f, s2 = 0.f;
#pragma unroll
    for (int q = 0; q < 8; ++q) {
        int f = lane + q * 32;
        float v = hr[f];
        s1 = fmaf(v, a[f], s1);
        s2 = fmaf(v, a[F_OUT + f], s2);
    }
#pragma unroll
    for (int off = 16; off > 0; off >>= 1) {
        s1 += __shfl_xor_sync(0xffffffffu, s1, off);
        s2 += __shfl_xor_sync(0xffffffffu, s2, off);
    }
    if (lane == 0) { g_f1[row] = s1; g_f2[row] = s2; }
}

// ===========================================================================
// Kernel 3: per-row softmax stats (max m, inverse denom 1/l)
// One warp per row; each lane owns strided chunks of 8.
// ===========================================================================
__global__ __launch_bounds__(256) void rowstats_kernel(const int* __restrict__ adj)
{
    const int warp = threadIdx.x >> 5;
    const int lane = threadIdx.x & 31;
    const int row  = blockIdx.x * 8 + warp;

    const int* arow = adj + (size_t)row * NN;
    const float f1v = g_f1[row];

    float m = -3.402823466e38f;
    float l = 0.f;

    for (int j0 = lane * 8; j0 < NN; j0 += 256) {
        int4   A0 = *(const int4*)&arow[j0];
        int4   A1 = *(const int4*)&arow[j0 + 4];
        float4 F0 = *(const float4*)&g_f2[j0];
        float4 F1 = *(const float4*)&g_f2[j0 + 4];

        int   av[8] = {A0.x, A0.y, A0.z, A0.w, A1.x, A1.y, A1.z, A1.w};
        float fv[8] = {F0.x, F0.y, F0.z, F0.w, F1.x, F1.y, F1.z, F1.w};
        float sv[8];
#pragma unroll
        for (int k = 0; k < 8; ++k) {
            float e = f1v + fv[k];
            e = (e > 0.f) ? e : ALPHA * e;
            sv[k] = (av[k] > 0) ? e : NEG_INF;
        }
        float cm = sv[0];
#pragma unroll
        for (int k = 1; k < 8; ++k) cm = fmaxf(cm, sv[k]);

        float mn = fmaxf(m, cm);
        float s = 0.f;
#pragma unroll
        for (int k = 0; k < 8; ++k) s += __expf(sv[k] - mn);
        l = l * __expf(m - mn) + s;
        m = mn;
    }

#pragma unroll
    for (int off = 16; off > 0; off >>= 1) {
        float m2 = __shfl_xor_sync(0xffffffffu, m, off);
        float l2 = __shfl_xor_sync(0xffffffffu, l, off);
        float mn = fmaxf(m, m2);
        l = l * __expf(m - mn) + l2 * __expf(m2 - mn);
        m = mn;
    }
    if (lane == 0) {
        g_m[row]  = m;
        g_il[row] = (l > 0.f) ? 1.f / l : 0.f;
    }
}

// ===========================================================================
// Kernel 4: att @ h via tf32 mma.sync, fused p-build + ELU epilogue.
// Block: 256 threads (8 warps), BM=64 rows, full F_OUT=256 cols, j-tile 32.
// Warp w: m-tile (w&3)*16, n-half (w>>2)*128. Each warp: 16 x m16n8k8 per
// k-step, 4 k-steps per j-tile.
// ===========================================================================
#define BM2 64
#define BN2 32
#define PS  36   // p_s row stride (4g+tg conflict-free for A frags)
#define HS  264  // h_s row stride (8tg+g conflict-free for B frags)

__global__ __launch_bounds__(256) void gat_mma_kernel(
    const int* __restrict__ adj, float* __restrict__ out)
{
    __shared__ float p_s[BM2][PS];
    __shared__ float h_s[BN2][HS];

    const int t    = threadIdx.x;
    const int warp = t >> 5;
    const int lane = t & 31;
    const int rowbase = blockIdx.x * BM2;

    // mma mapping
    const int mrow = (warp & 3) * 16;
    const int ncol = (warp >> 2) * 128;
    const int g  = lane >> 2;   // 0..7
    const int tg = lane & 3;    // 0..3

    // p-build mapping: thread -> (row pr, 8 j starting at pj)
    const int pr = t >> 2;          // 0..63
    const int pj = (t & 3) * 8;     // 0,8,16,24
    const float f1v  = g_f1[rowbase + pr];
    const float rm   = g_m [rowbase + pr];
    const float invl = g_il[rowbase + pr];

    float c[16][4];
#pragma unroll
    for (int nt = 0; nt < 16; ++nt)
#pragma unroll
        for (int q = 0; q < 4; ++q) c[nt][q] = 0.f;

    for (int j0 = 0; j0 < NN; j0 += BN2) {
        // ---- stage h tile (already tf32-rounded) -----------------------
#pragma unroll
        for (int q = 0; q < 8; ++q) {
            int fi = q * 256 + t;          // float4 index 0..2047
            int jj = fi >> 6;
            int ff = (fi & 63) * 4;
            *(float4*)&h_s[jj][ff] =
                *(const float4*)&g_ht[(size_t)(j0 + jj) * F_OUT + ff];
        }

        // ---- build normalized p tile (tf32) ----------------------------
        {
            const int* arow = adj + (size_t)(rowbase + pr) * NN + j0 + pj;
            int4   A0 = *(const int4*)arow;
            int4   A1 = *(const int4*)(arow + 4);
            float4 F0 = *(const float4*)&g_f2[j0 + pj];
            float4 F1 = *(const float4*)&g_f2[j0 + pj + 4];

            int   av[8] = {A0.x, A0.y, A0.z, A0.w, A1.x, A1.y, A1.z, A1.w};
            float fv[8] = {F0.x, F0.y, F0.z, F0.w, F1.x, F1.y, F1.z, F1.w};
            float pv[8];
#pragma unroll
            for (int k = 0; k < 8; ++k) {
                float e = f1v + fv[k];
                e = (e > 0.f) ? e : ALPHA * e;
                float sv = (av[k] > 0) ? e : NEG_INF;
                pv[k] = to_tf32(__expf(sv - rm) * invl);
            }
            *(float4*)&p_s[pr][pj]     = make_float4(pv[0], pv[1], pv[2], pv[3]);
            *(float4*)&p_s[pr][pj + 4] = make_float4(pv[4], pv[5], pv[6], pv[7]);
        }
        __syncthreads();

        // ---- tensor-core GEMM on this tile -----------------------------
#pragma unroll
        for (int ks = 0; ks < 4; ++ks) {
            int kb = ks * 8;
            uint32_t a0 = __float_as_uint(p_s[mrow + g    ][kb + tg    ]);
            uint32_t a1 = __float_as_uint(p_s[mrow + g + 8][kb + tg    ]);
            uint32_t a2 = __float_as_uint(p_s[mrow + g    ][kb + tg + 4]);
            uint32_t a3 = __float_as_uint(p_s[mrow + g + 8][kb + tg + 4]);
#pragma unroll
            for (int nt = 0; nt < 16; ++nt) {
                int n0 = ncol + nt * 8;
                uint32_t b0 = __float_as_uint(h_s[kb + tg    ][n0 + g]);
                uint32_t b1 = __float_as_uint(h_s[kb + tg + 4][n0 + g]);
                asm volatile(
                    "mma.sync.aligned.m16n8k8.row.col.f32.tf32.tf32.f32 "
                    "{%0,%1,%2,%3}, {%4,%5,%6,%7}, {%8,%9}, {%0,%1,%2,%3};"
                    : "+f"(c[nt][0]), "+f"(c[nt][1]), "+f"(c[nt][2]), "+f"(c[nt][3])
                    : "r"(a0), "r"(a1), "r"(a2), "r"(a3), "r"(b0), "r"(b1));
            }
        }
        __syncthreads();
    }

    // ---- epilogue: ELU + store ----------------------------------------
    const int row0 = rowbase + mrow + g;
    const int row1 = row0 + 8;
#pragma unroll
    for (int nt = 0; nt < 16; ++nt) {
        int col = ncol + nt * 8 + tg * 2;
        float v0 = c[nt][0], v1 = c[nt][1], v2 = c[nt][2], v3 = c[nt][3];
        v0 = (v0 > 0.f) ? v0 : (__expf(v0) - 1.f);
        v1 = (v1 > 0.f) ? v1 : (__expf(v1) - 1.f);
        v2 = (v2 > 0.f) ? v2 : (__expf(v2) - 1.f);
        v3 = (v3 > 0.f) ? v3 : (__expf(v3) - 1.f);
        *(float2*)&out[(size_t)row0 * F_OUT + col] = make_float2(v0, v1);
        *(float2*)&out[(size_t)row1 * F_OUT + col] = make_float2(v2, v3);
    }
}

// ===========================================================================
// launch
// ===========================================================================
extern "C" void kernel_launch(void* const* d_in, const int* in_sizes, int n_in,
                              void* d_out, int out_size)
{
    const float* x   = (const float*)d_in[0];   // [8192, 512]
    const int*   adj = (const int*)  d_in[1];   // [8192, 8192]
    const float* W   = (const float*)d_in[2];   // [512, 256]
    const float* a   = (const float*)d_in[3];   // [512, 1]
    float* out = (float*)d_out;                 // [8192, 256]

    gemm1_kernel<<<dim3(NN / 64, F_OUT / 64), 256>>>(x, W);
    f12_kernel<<<NN / 8, 256>>>(a);
    rowstats_kernel<<<NN / 8, 256>>>(adj);
    gat_mma_kernel<<<NN / BM2, 256>>>(adj, out);
}

// round 6
// speedup vs baseline: 2.5383x; 1.3848x over previous
#include <cuda_runtime.h>
#include <cuda_fp16.h>
#include <cstdint>

// Problem constants
#define NN    8192
#define F_IN  512
#define F_OUT 256
#define ALPHA 0.2f
#define NEG_INF (-9e15f)

// -------- scratch (device globals: no allocations allowed) ----------------
__device__ float g_h [NN * F_OUT];  // h = x @ W (fp32, for f1/f2)
__device__ float g_ht[NN * F_OUT];  // h pre-rounded to tf32 (mma B operand)
__device__ float g_f1[NN];
__device__ float g_f2[NN];
__device__ float g_m [NN];          // row max of masked scores
__device__ float g_il[NN];          // 1 / row softmax denom

__device__ __forceinline__ float to_tf32(float x) {
    uint32_t r;
    asm("cvt.rna.tf32.f32 %0, %1;" : "=r"(r) : "f"(x));
    return __uint_as_float(r);
}

__device__ __forceinline__ uint32_t smem_u32(const void* p) {
    uint32_t a;
    asm("{ .reg .u64 t; cvta.to.shared.u64 t, %1; cvt.u32.u64 %0, t; }"
        : "=r"(a) : "l"(p));
    return a;
}

// ===========================================================================
// Kernel 1: h = x @ W  (8192x512 @ 512x256); fp32 h + tf32-rounded copy
// ===========================================================================
__global__ __launch_bounds__(256) void gemm1_kernel(
    const float* __restrict__ X, const float* __restrict__ W)
{
    __shared__ float Xs[16][64];
    __shared__ float Ws[16][64];

    const int t   = threadIdx.x;
    const int tx  = t & 15;
    const int ty  = t >> 4;
    const int row0 = blockIdx.x * 64;
    const int col0 = blockIdx.y * 64;

    float acc[4][4];
#pragma unroll
    for (int i = 0; i < 4; ++i)
#pragma unroll
        for (int j = 0; j < 4; ++j) acc[i][j] = 0.f;

    for (int k0 = 0; k0 < F_IN; k0 += 16) {
        {
            int r  = t >> 2;
            int kq = (t & 3) * 4;
            float4 v = *(const float4*)&X[(size_t)(row0 + r) * F_IN + k0 + kq];
            Xs[kq + 0][r] = v.x;
            Xs[kq + 1][r] = v.y;
            Xs[kq + 2][r] = v.z;
            Xs[kq + 3][r] = v.w;
        }
        {
            int kr = t >> 4;
            int cq = (t & 15) * 4;
            *(float4*)&Ws[kr][cq] =
                *(const float4*)&W[(size_t)(k0 + kr) * F_OUT + col0 + cq];
        }
        __syncthreads();

#pragma unroll
        for (int kk = 0; kk < 16; ++kk) {
            float a4[4], b4[4];
            *(float4*)a4 = *(const float4*)&Xs[kk][ty * 4];
            *(float4*)b4 = *(const float4*)&Ws[kk][tx * 4];
#pragma unroll
            for (int i = 0; i < 4; ++i)
#pragma unroll
                for (int j = 0; j < 4; ++j)
                    acc[i][j] = fmaf(a4[i], b4[j], acc[i][j]);
        }
        __syncthreads();
    }

#pragma unroll
    for (int i = 0; i < 4; ++i) {
        size_t off = (size_t)(row0 + ty * 4 + i) * F_OUT + col0 + tx * 4;
        *(float4*)&g_h[off]  = make_float4(acc[i][0], acc[i][1], acc[i][2], acc[i][3]);
        *(float4*)&g_ht[off] = make_float4(to_tf32(acc[i][0]), to_tf32(acc[i][1]),
                                           to_tf32(acc[i][2]), to_tf32(acc[i][3]));
    }
}

// ===========================================================================
// Kernel 2: f1 / f2 row dot products
// ===========================================================================
__global__ __launch_bounds__(256) void f12_kernel(const float* __restrict__ a)
{
    const int warp = threadIdx.x >> 5;
    const int lane = threadIdx.x & 31;
    const int row  = blockIdx.x * 8 + warp;
    if (row >= NN) return;

    const float* hr = &g_h[(size_t)row * F_OUT];
    float s1 = 0.f, s2 = 0.f;
#pragma unroll
    for (int q = 0; q < 8; ++q) {
        int f = lane + q * 32;
        float v = hr[f];
        s1 = fmaf(v, a[f], s1);
        s2 = fmaf(v, a[F_OUT + f], s2);
    }
#pragma unroll
    for (int off = 16; off > 0; off >>= 1) {
        s1 += __shfl_xor_sync(0xffffffffu, s1, off);
        s2 += __shfl_xor_sync(0xffffffffu, s2, off);
    }
    if (lane == 0) { g_f1[row] = s1; g_f2[row] = s2; }
}

// ===========================================================================
// Kernel 3: per-row softmax stats (max m, inverse denom 1/l)
// ===========================================================================
__global__ __launch_bounds__(256) void rowstats_kernel(const int* __restrict__ adj)
{
    const int warp = threadIdx.x >> 5;
    const int lane = threadIdx.x & 31;
    const int row  = blockIdx.x * 8 + warp;

    const int* arow = adj + (size_t)row * NN;
    const float f1v = g_f1[row];

    float m = -3.402823466e38f;
    float l = 0.f;

    for (int j0 = lane * 8; j0 < NN; j0 += 256) {
        int4   A0 = *(const int4*)&arow[j0];
        int4   A1 = *(const int4*)&arow[j0 + 4];
        float4 F0 = *(const float4*)&g_f2[j0];
        float4 F1 = *(const float4*)&g_f2[j0 + 4];

        int   av[8] = {A0.x, A0.y, A0.z, A0.w, A1.x, A1.y, A1.z, A1.w};
        float fv[8] = {F0.x, F0.y, F0.z, F0.w, F1.x, F1.y, F1.z, F1.w};
        float sv[8];
#pragma unroll
        for (int k = 0; k < 8; ++k) {
            float e = f1v + fv[k];
            e = (e > 0.f) ? e : ALPHA * e;
            sv[k] = (av[k] > 0) ? e : NEG_INF;
        }
        float cm = sv[0];
#pragma unroll
        for (int k = 1; k < 8; ++k) cm = fmaxf(cm, sv[k]);

        float mn = fmaxf(m, cm);
        float s = 0.f;
#pragma unroll
        for (int k = 0; k < 8; ++k) s += __expf(sv[k] - mn);
        l = l * __expf(m - mn) + s;
        m = mn;
    }

#pragma unroll
    for (int off = 16; off > 0; off >>= 1) {
        float m2 = __shfl_xor_sync(0xffffffffu, m, off);
        float l2 = __shfl_xor_sync(0xffffffffu, l, off);
        float mn = fmaxf(m, m2);
        l = l * __expf(m - mn) + l2 * __expf(m2 - mn);
        m = mn;
    }
    if (lane == 0) {
        g_m[row]  = m;
        g_il[row] = (l > 0.f) ? 1.f / l : 0.f;
    }
}

// ===========================================================================
// Kernel 4: att @ h via tf32 mma m16n8k8, software-pipelined, double-buffered.
// 256 threads (8 warps), BM=32 rows/block (grid 256), j-tile 32.
// Each warp: all 32 rows (2 m16 tiles) x 32 cols (4 n8 tiles), 4 k8 steps.
// p stored UNNORMALIZED exp(e-m) as tf32; 1/l applied in fp32 epilogue.
// ===========================================================================
#define BM2    32
#define BN2    32
#define NT     (NN / BN2)           // 256 tiles
#define PS     36                   // p_s row stride (floats)
#define HS     264                  // h_s row stride (floats)
#define HBUF_F (BN2 * HS)           // 8448 floats per h buffer
#define PBUF_F (BM2 * PS)           // 1152 floats per p buffer
#define SMEM_BYTES ((2 * HBUF_F + 2 * PBUF_F) * 4)

__global__ __launch_bounds__(256) void gat_mma_kernel(
    const int* __restrict__ adj, float* __restrict__ out)
{
    extern __shared__ float smemf[];
    float* h_s = smemf;                  // [2][BN2][HS]
    float* p_s = smemf + 2 * HBUF_F;     // [2][BM2][PS]
    const uint32_t h_a = smem_u32(h_s);

    const int t    = threadIdx.x;
    const int warp = t >> 5;
    const int lane = t & 31;
    const int rowbase = blockIdx.x * BM2;

    // mma mapping: warp covers all 32 rows x cols [warp*32, warp*32+32)
    const int ncol = warp * 32;
    const int gr   = lane >> 2;      // 0..7
    const int tg   = lane & 3;       // 0..3

    // p-build mapping: thread -> row pr, 4 j at pj
    const int pr = t >> 3;           // 0..31
    const int pj = (t & 7) * 4;      // 0..28
    const float f1v = g_f1[rowbase + pr];
    const float rm  = g_m [rowbase + pr];
    const int* arow = adj + (size_t)(rowbase + pr) * NN;

    float c[2][4][4];                // [m-tile][n-tile][frag]
#pragma unroll
    for (int mt = 0; mt < 2; ++mt)
#pragma unroll
        for (int nt = 0; nt < 4; ++nt)
#pragma unroll
            for (int q = 0; q < 4; ++q) c[mt][nt][q] = 0.f;

    // ---------------- prologue: tile 0 ---------------------------------
    float4 phv;
    {
        int4   A0 = *(const int4*)&arow[pj];
        float4 F0 = *(const float4*)&g_f2[pj];
        int   av[4] = {A0.x, A0.y, A0.z, A0.w};
        float fv[4] = {F0.x, F0.y, F0.z, F0.w};
        float pv[4];
#pragma unroll
        for (int k = 0; k < 4; ++k) {
            float e = f1v + fv[k];
            e = (e > 0.f) ? e : ALPHA * e;
            float sv = (av[k] > 0) ? e : NEG_INF;
            pv[k] = to_tf32(__expf(sv - rm));   // unnormalized, (0,1]
        }
        phv = make_float4(pv[0], pv[1], pv[2], pv[3]);
    }
    // cp.async h tile 0 into buffer 0
    {
#pragma unroll
        for (int q = 0; q < 8; ++q) {
            int fi = q * 256 + t;            // float4 idx 0..2047
            int jj = fi >> 6;
            int ff = (fi & 63) * 4;
            uint32_t dst = h_a + (uint32_t)(jj * HS + ff) * 4;
            const float* src = &g_ht[(size_t)jj * F_OUT + ff];
            asm volatile("cp.async.cg.shared.global [%0], [%1], 16;\n"
                         :: "r"(dst), "l"(src));
        }
        asm volatile("cp.async.commit_group;\n" ::: "memory");
    }

    // ---------------- main loop ----------------------------------------
    for (int it = 0; it < NT; ++it) {
        const int buf = it & 1;
        const bool more = (it + 1 < NT);
        int4   nA;
        float4 nF;

        if (more) {
            int jn = (it + 1) * BN2;
            // prefetch next h tile
#pragma unroll
            for (int q = 0; q < 8; ++q) {
                int fi = q * 256 + t;
                int jj = fi >> 6;
                int ff = (fi & 63) * 4;
                uint32_t dst = h_a + (uint32_t)((buf ^ 1) * HBUF_F + jj * HS + ff) * 4;
                const float* src = &g_ht[(size_t)(jn + jj) * F_OUT + ff];
                asm volatile("cp.async.cg.shared.global [%0], [%1], 16;\n"
                             :: "r"(dst), "l"(src));
            }
            asm volatile("cp.async.commit_group;\n" ::: "memory");
            // prefetch next adj / f2
            nA = *(const int4*)&arow[jn + pj];
            nF = *(const float4*)&g_f2[jn + pj];
        }

        // store this tile's p
        *(float4*)&p_s[buf * PBUF_F + pr * PS + pj] = phv;

        if (more) asm volatile("cp.async.wait_group 1;\n" ::: "memory");
        else      asm volatile("cp.async.wait_group 0;\n" ::: "memory");
        __syncthreads();

        // ---- tensor-core GEMM on this tile -----------------------------
        const float* pb = &p_s[buf * PBUF_F];
        const float* hb = &h_s[buf * HBUF_F];
#pragma unroll
        for (int ks = 0; ks < 4; ++ks) {
            int kb = ks * 8;
            uint32_t a[2][4];
#pragma unroll
            for (int mt = 0; mt < 2; ++mt) {
                int r0 = mt * 16 + gr;
                a[mt][0] = __float_as_uint(pb[r0      * PS + kb + tg]);
                a[mt][1] = __float_as_uint(pb[(r0 + 8) * PS + kb + tg]);
                a[mt][2] = __float_as_uint(pb[r0      * PS + kb + tg + 4]);
                a[mt][3] = __float_as_uint(pb[(r0 + 8) * PS + kb + tg + 4]);
            }
#pragma unroll
            for (int nt = 0; nt < 4; ++nt) {
                int n0 = ncol + nt * 8 + gr;
                uint32_t b0 = __float_as_uint(hb[(kb + tg)     * HS + n0]);
                uint32_t b1 = __float_as_uint(hb[(kb + tg + 4) * HS + n0]);
#pragma unroll
                for (int mt = 0; mt < 2; ++mt) {
                    asm volatile(
                        "mma.sync.aligned.m16n8k8.row.col.f32.tf32.tf32.f32 "
                        "{%0,%1,%2,%3}, {%4,%5,%6,%7}, {%8,%9}, {%0,%1,%2,%3};"
                        : "+f"(c[mt][nt][0]), "+f"(c[mt][nt][1]),
                          "+f"(c[mt][nt][2]), "+f"(c[mt][nt][3])
                        : "r"(a[mt][0]), "r"(a[mt][1]), "r"(a[mt][2]), "r"(a[mt][3]),
                          "r"(b0), "r"(b1));
                }
            }
        }

        // ---- build next tile's p ---------------------------------------
        if (more) {
            int   av[4] = {nA.x, nA.y, nA.z, nA.w};
            float fv[4] = {nF.x, nF.y, nF.z, nF.w};
            float pv[4];
#pragma unroll
            for (int k = 0; k < 4; ++k) {
                float e = f1v + fv[k];
                e = (e > 0.f) ? e : ALPHA * e;
                float sv = (av[k] > 0) ? e : NEG_INF;
                pv[k] = to_tf32(__expf(sv - rm));
            }
            phv = make_float4(pv[0], pv[1], pv[2], pv[3]);
        }
    }

    // ---- epilogue: normalize by 1/l, ELU, store -----------------------
#pragma unroll
    for (int mt = 0; mt < 2; ++mt) {
        int row0 = rowbase + mt * 16 + gr;
        int row1 = row0 + 8;
        float il0 = g_il[row0];
        float il1 = g_il[row1];
#pragma unroll
        for (int nt = 0; nt < 4; ++nt) {
            int col = ncol + nt * 8 + tg * 2;
            float v0 = c[mt][nt][0] * il0, v1 = c[mt][nt][1] * il0;
            float v2 = c[mt][nt][2] * il1, v3 = c[mt][nt][3] * il1;
            v0 = (v0 > 0.f) ? v0 : (__expf(v0) - 1.f);
            v1 = (v1 > 0.f) ? v1 : (__expf(v1) - 1.f);
            v2 = (v2 > 0.f) ? v2 : (__expf(v2) - 1.f);
            v3 = (v3 > 0.f) ? v3 : (__expf(v3) - 1.f);
            *(float2*)&out[(size_t)row0 * F_OUT + col] = make_float2(v0, v1);
            *(float2*)&out[(size_t)row1 * F_OUT + col] = make_float2(v2, v3);
        }
    }
}

// ===========================================================================
// launch
// ===========================================================================
extern "C" void kernel_launch(void* const* d_in, const int* in_sizes, int n_in,
                              void* d_out, int out_size)
{
    const float* x   = (const float*)d_in[0];   // [8192, 512]
    const int*   adj = (const int*)  d_in[1];   // [8192, 8192]
    const float* W   = (const float*)d_in[2];   // [512, 256]
    const float* a   = (const float*)d_in[3];   // [512, 1]
    float* out = (float*)d_out;                 // [8192, 256]

    cudaFuncSetAttribute(gat_mma_kernel,
                         cudaFuncAttributeMaxDynamicSharedMemorySize, SMEM_BYTES);

    gemm1_kernel<<<dim3(NN / 64, F_OUT / 64), 256>>>(x, W);
    f12_kernel<<<NN / 8, 256>>>(a);
    rowstats_kernel<<<NN / 8, 256>>>(adj);
    gat_mma_kernel<<<NN / BM2, 256, SMEM_BYTES>>>(adj, out);
}